// round 8
// baseline (speedup 1.0000x reference)
#include <cuda_runtime.h>

// ---------------------------------------------------------------------------
// MixGAT: 2-layer GAT on a random graph with self-loops.
//   N=50000 nodes, E=800000 edges (+N self loops), IN=256, H=4, HID=64, OUT=64
// R8 == R7 resubmission (broker flake; theory untested):
//   - per-edge exp(leakyrelu(...)) precomputed ONCE per (edge,head) in a
//     dedicated kernel (was recomputed 16x redundantly by the aggregation
//     threads); aggregation loops now load the precomputed scalar
//   - scatter kernel additionally records dst per CSR slot (g_edst)
// ---------------------------------------------------------------------------

#define N_NODES 50000
#define N_EDGES 800000
#define ETOT    (N_EDGES + N_NODES)
#define DIN     256
#define NH      4
#define HID     64
#define D1      256   // NH*HID
#define DOUT    64
#define SLOPE   0.2f
#define BETA    0.5f

// ---- scratch (device globals: allocation is forbidden) ----
__device__ float g_h1[N_NODES * D1];     // 51.2 MB
__device__ float g_x1[N_NODES * D1];     // 51.2 MB
__device__ float g_h2[N_NODES * DOUT];   // 12.8 MB
__device__ float g_s1s[N_NODES * NH];
__device__ float g_s1d[N_NODES * NH];
__device__ float g_s2s[N_NODES];
__device__ float g_s2d[N_NODES];
__device__ int   g_deg[N_NODES];
__device__ int   g_rowptr[N_NODES + 1];
__device__ int   g_wptr[N_NODES];
__device__ int   g_csr[ETOT];            // src node per (dst-sorted) edge
__device__ int   g_edst[ETOT];           // dst node per (dst-sorted) edge
__device__ float4 g_ee1[ETOT];           // exp(lrelu(e)) per edge, 4 heads (13.6MB)
__device__ float  g_ee2[ETOT];           // layer-2 (3.4MB)

// ---------------------------------------------------------------------------
// CSR build
// ---------------------------------------------------------------------------
__global__ void zero_deg_kernel(int n) {
    int i = blockIdx.x * blockDim.x + threadIdx.x;
    if (i < n) g_deg[i] = 0;
}

__global__ void count_edges_kernel(const int* __restrict__ ei, int E, int n) {
    int j = blockIdx.x * blockDim.x + threadIdx.x;
    int etot = E + n;
    if (j >= etot) return;
    int dst = (j < E) ? ei[E + j] : (j - E);  // self loops appended
    atomicAdd(&g_deg[dst], 1);
}

// single-block exclusive scan over g_deg -> g_rowptr, g_wptr
__global__ void scan_kernel(int n) {
    __shared__ int sh[1024];
    __shared__ int carry;
    int tid = threadIdx.x;
    if (tid == 0) carry = 0;
    __syncthreads();
    for (int base = 0; base < n; base += 1024) {
        int i = base + tid;
        int v = (i < n) ? g_deg[i] : 0;
        sh[tid] = v;
        __syncthreads();
        int val = v;
        #pragma unroll
        for (int off = 1; off < 1024; off <<= 1) {
            int t = (tid >= off) ? sh[tid - off] : 0;
            __syncthreads();
            val += t;
            sh[tid] = val;
            __syncthreads();
        }
        int excl = val - v;
        int c = carry;
        if (i < n) { g_rowptr[i] = c + excl; g_wptr[i] = c + excl; }
        __syncthreads();
        if (tid == 0) carry = c + sh[1023];
        __syncthreads();
    }
    if (tid == 0) g_rowptr[n] = carry;
}

__global__ void scatter_edges_kernel(const int* __restrict__ ei, int E, int n) {
    int j = blockIdx.x * blockDim.x + threadIdx.x;
    int etot = E + n;
    if (j >= etot) return;
    int src, dst;
    if (j < E) { src = ei[j]; dst = ei[E + j]; }
    else       { src = dst = j - E; }
    int p = atomicAdd(&g_wptr[dst], 1);
    g_csr[p] = src;
    g_edst[p] = dst;
}

// ---------------------------------------------------------------------------
// SGEMM: C[M,N] = A[M,K] @ B[K,N], row-major fp32, 256 threads.
// BK=16, register-prefetch double buffering (no lambdas).
// (BM/TM)*(BN/TN) == 256. K,N multiples of BK/BN; M guarded.
// ---------------------------------------------------------------------------
template <int BM, int BN, int BK, int TM, int TN>
__global__ __launch_bounds__(256) void sgemm_kernel(
    int M, int N, int K,
    const float* __restrict__ A, const float* __restrict__ B,
    float* __restrict__ C)
{
    const int NA = (BM * BK) / (256 * 4);   // float4 A-loads per thread
    const int NB = (BK * BN) / (256 * 4);   // float4 B-loads per thread
    __shared__ float As[BK][BM];
    __shared__ float Bs[BK][BN];
    const int tid = threadIdx.x;
    const int tx = tid % (BN / TN);
    const int ty = tid / (BN / TN);
    const int rowBase = blockIdx.y * BM;
    const int colBase = blockIdx.x * BN;

    float acc[TM][TN];
    #pragma unroll
    for (int m = 0; m < TM; m++)
        #pragma unroll
        for (int n = 0; n < TN; n++) acc[m][n] = 0.f;

    float4 ra[(BM * BK) / (256 * 4)];
    float4 rb[(BK * BN) / (256 * 4)];

    // prefetch first tile
    #pragma unroll
    for (int i = 0; i < NA; i++) {
        int idx = (tid + i * 256) * 4;
        int r = idx / BK, c = idx % BK;
        int gr = rowBase + r;
        if (gr < M) ra[i] = *(const float4*)(A + (long)gr * K + c);
        else        ra[i] = make_float4(0.f, 0.f, 0.f, 0.f);
    }
    #pragma unroll
    for (int i = 0; i < NB; i++) {
        int idx = (tid + i * 256) * 4;
        int r = idx / BN, c = idx % BN;
        rb[i] = *(const float4*)(B + (long)r * N + colBase + c);
    }

    for (int k0 = 0; k0 < K; k0 += BK) {
        #pragma unroll
        for (int i = 0; i < NA; i++) {
            int idx = (tid + i * 256) * 4;
            int r = idx / BK, c = idx % BK;
            As[c + 0][r] = ra[i].x; As[c + 1][r] = ra[i].y;
            As[c + 2][r] = ra[i].z; As[c + 3][r] = ra[i].w;
        }
        #pragma unroll
        for (int i = 0; i < NB; i++) {
            int idx = (tid + i * 256) * 4;
            int r = idx / BN, c = idx % BN;
            *(float4*)&Bs[r][c] = rb[i];
        }
        __syncthreads();

        int k1 = k0 + BK;
        if (k1 < K) {
            #pragma unroll
            for (int i = 0; i < NA; i++) {
                int idx = (tid + i * 256) * 4;
                int r = idx / BK, c = idx % BK;
                int gr = rowBase + r;
                if (gr < M) ra[i] = *(const float4*)(A + (long)gr * K + k1 + c);
                else        ra[i] = make_float4(0.f, 0.f, 0.f, 0.f);
            }
            #pragma unroll
            for (int i = 0; i < NB; i++) {
                int idx = (tid + i * 256) * 4;
                int r = idx / BN, c = idx % BN;
                rb[i] = *(const float4*)(B + (long)(k1 + r) * N + colBase + c);
            }
        }

        #pragma unroll
        for (int k = 0; k < BK; k++) {
            float af[TM], bf[TN];
            #pragma unroll
            for (int m = 0; m < TM; m++) af[m] = As[k][ty * TM + m];
            #pragma unroll
            for (int n = 0; n < TN; n++) bf[n] = Bs[k][tx * TN + n];
            #pragma unroll
            for (int m = 0; m < TM; m++)
                #pragma unroll
                for (int n = 0; n < TN; n++) acc[m][n] += af[m] * bf[n];
        }
        __syncthreads();
    }

    #pragma unroll
    for (int m = 0; m < TM; m++) {
        int gr = rowBase + ty * TM + m;
        if (gr >= M) continue;
        #pragma unroll
        for (int n = 0; n < TN; n += 4) {
            *(float4*)(C + (long)gr * N + colBase + tx * TN + n) =
                make_float4(acc[m][n], acc[m][n + 1], acc[m][n + 2], acc[m][n + 3]);
        }
    }
}

// ---------------------------------------------------------------------------
// attention logits: s_src[i,h] = sum_f h1[i,h,f]*a_src[h,f]  (and dst)
// ---------------------------------------------------------------------------
__global__ __launch_bounds__(256) void s1_kernel(
    const float* __restrict__ a_src, const float* __restrict__ a_dst, int n)
{
    int warp = (blockIdx.x * blockDim.x + threadIdx.x) >> 5;
    int lane = threadIdx.x & 31;
    if (warp >= n) return;
    const float* row = g_h1 + (long)warp * D1;
    float accs[4] = {0.f, 0.f, 0.f, 0.f};
    float accd[4] = {0.f, 0.f, 0.f, 0.f};
    #pragma unroll
    for (int j = 0; j < 8; j++) {
        int k = lane + 32 * j;          // head = j>>1
        float v = row[k];
        accs[j >> 1] += v * a_src[k];
        accd[j >> 1] += v * a_dst[k];
    }
    #pragma unroll
    for (int h = 0; h < 4; h++) {
        float s = accs[h], d = accd[h];
        #pragma unroll
        for (int off = 16; off; off >>= 1) {
            s += __shfl_down_sync(0xffffffffu, s, off);
            d += __shfl_down_sync(0xffffffffu, d, off);
        }
        if (lane == 0) { g_s1s[warp * NH + h] = s; g_s1d[warp * NH + h] = d; }
    }
}

__global__ __launch_bounds__(256) void s2_kernel(
    const float* __restrict__ a_src, const float* __restrict__ a_dst, int n)
{
    int warp = (blockIdx.x * blockDim.x + threadIdx.x) >> 5;
    int lane = threadIdx.x & 31;
    if (warp >= n) return;
    const float* row = g_h2 + (long)warp * DOUT;
    float v0 = row[lane], v1 = row[lane + 32];
    float s = v0 * a_src[lane] + v1 * a_src[lane + 32];
    float d = v0 * a_dst[lane] + v1 * a_dst[lane + 32];
    #pragma unroll
    for (int off = 16; off; off >>= 1) {
        s += __shfl_down_sync(0xffffffffu, s, off);
        d += __shfl_down_sync(0xffffffffu, d, off);
    }
    if (lane == 0) { g_s2s[warp] = s; g_s2d[warp] = d; }
}

// ---------------------------------------------------------------------------
// per-edge exp(leakyrelu(logit)) — computed ONCE per (edge, head).
// softmax is shift-invariant; logits are O(1) so exp() cannot overflow.
// ---------------------------------------------------------------------------
__global__ __launch_bounds__(256) void edge1_kernel(int etot)
{
    int j = blockIdx.x * blockDim.x + threadIdx.x;
    if (j >= etot) return;
    int src = g_csr[j], dst = g_edst[j];
    const float4 ss = *(const float4*)(g_s1s + src * NH);
    const float4 dd = *(const float4*)(g_s1d + dst * NH);
    float4 o;
    float e;
    e = ss.x + dd.x; e = (e > 0.f) ? e : SLOPE * e; o.x = __expf(e);
    e = ss.y + dd.y; e = (e > 0.f) ? e : SLOPE * e; o.y = __expf(e);
    e = ss.z + dd.z; e = (e > 0.f) ? e : SLOPE * e; o.z = __expf(e);
    e = ss.w + dd.w; e = (e > 0.f) ? e : SLOPE * e; o.w = __expf(e);
    g_ee1[j] = o;
}

__global__ __launch_bounds__(256) void edge2_kernel(int etot)
{
    int j = blockIdx.x * blockDim.x + threadIdx.x;
    if (j >= etot) return;
    float e = g_s2s[g_csr[j]] + g_s2d[g_edst[j]];
    e = (e > 0.f) ? e : SLOPE * e;
    g_ee2[j] = __expf(e);
}

// ---------------------------------------------------------------------------
// GAT layer 1 aggregate: 64 threads per node (4 nodes/block), float4 features.
// Edge weights are precomputed (g_ee1); loop is a pure gather+FMA.
// ---------------------------------------------------------------------------
__global__ __launch_bounds__(256) void gat1_kernel(const float* __restrict__ b1, int n)
{
    int node = blockIdx.x * 4 + (threadIdx.x >> 6);
    if (node >= n) return;
    int local = threadIdx.x & 63;        // 0..63 -> float4 index in the 256-row
    int head = local >> 4;
    int beg = g_rowptr[node], end = g_rowptr[node + 1];

    const float4* h1v = (const float4*)g_h1;
    const float* ee1 = (const float*)g_ee1;
    float denom = 0.f;
    float4 acc = make_float4(0.f, 0.f, 0.f, 0.f);
    #pragma unroll 2
    for (int j = beg; j < end; j++) {
        int src = g_csr[j];
        float ee = ee1[(j << 2) + head];
        denom += ee;
        float4 h = h1v[(long)src * (D1 / 4) + local];
        acc.x += ee * h.x; acc.y += ee * h.y;
        acc.z += ee * h.z; acc.w += ee * h.w;
    }
    float inv = 1.f / denom;
    float z0 = acc.x * inv + b1[local * 4 + 0];
    float z1 = acc.y * inv + b1[local * 4 + 1];
    float z2 = acc.z * inv + b1[local * 4 + 2];
    float z3 = acc.w * inv + b1[local * 4 + 3];
    // beta-mix swish, CC=1: BETA*z + (1-BETA)*z*sigmoid(z)
    float4 o;
    o.x = BETA * z0 + (1.f - BETA) * z0 / (1.f + __expf(-z0));
    o.y = BETA * z1 + (1.f - BETA) * z1 / (1.f + __expf(-z1));
    o.z = BETA * z2 + (1.f - BETA) * z2 / (1.f + __expf(-z2));
    o.w = BETA * z3 + (1.f - BETA) * z3 / (1.f + __expf(-z3));
    *(float4*)(g_x1 + (long)node * D1 + local * 4) = o;
}

// GAT layer 2: 16 threads per node (16 nodes per 256-block), float4 features.
__global__ __launch_bounds__(256) void gat2_kernel(
    const float* __restrict__ b2, float* __restrict__ out, int n)
{
    int node = blockIdx.x * 16 + (threadIdx.x >> 4);
    if (node >= n) return;
    int local = threadIdx.x & 15;        // float4 index in the 64-row
    int beg = g_rowptr[node], end = g_rowptr[node + 1];

    const float4* h2v = (const float4*)g_h2;
    float denom = 0.f;
    float4 acc = make_float4(0.f, 0.f, 0.f, 0.f);
    #pragma unroll 2
    for (int j = beg; j < end; j++) {
        int src = g_csr[j];
        float ee = g_ee2[j];
        denom += ee;
        float4 h = h2v[(long)src * (DOUT / 4) + local];
        acc.x += ee * h.x; acc.y += ee * h.y;
        acc.z += ee * h.z; acc.w += ee * h.w;
    }
    float inv = 1.f / denom;
    float o0 = acc.x * inv + b2[local * 4 + 0];
    float o1 = acc.y * inv + b2[local * 4 + 1];
    float o2 = acc.z * inv + b2[local * 4 + 2];
    float o3 = acc.w * inv + b2[local * 4 + 3];
    float* op = out + (long)node * DOUT + local * 4;
    op[0] = o0; op[1] = o1; op[2] = o2; op[3] = o3;  // CC=1, heads=1
}

// ---------------------------------------------------------------------------
extern "C" void kernel_launch(void* const* d_in, const int* in_sizes, int n_in,
                              void* d_out, int out_size)
{
    const float* x   = (const float*)d_in[0];
    const int*   ei  = (const int*)d_in[1];
    const float* W1  = (const float*)d_in[2];
    const float* as1 = (const float*)d_in[3];
    const float* ad1 = (const float*)d_in[4];
    const float* b1  = (const float*)d_in[5];
    const float* W2  = (const float*)d_in[6];
    const float* as2 = (const float*)d_in[7];
    const float* ad2 = (const float*)d_in[8];
    const float* b2  = (const float*)d_in[9];
    float* out = (float*)d_out;

    const int n = in_sizes[0] / DIN;      // 50000
    const int E = in_sizes[1] / 2;        // 800000
    const int etot = E + n;

    float *h1, *x1, *h2;
    cudaGetSymbolAddress((void**)&h1, g_h1);
    cudaGetSymbolAddress((void**)&x1, g_x1);
    cudaGetSymbolAddress((void**)&h2, g_h2);

    // 1. CSR build by dst (shared by both layers)
    zero_deg_kernel<<<(n + 255) / 256, 256>>>(n);
    count_edges_kernel<<<(etot + 255) / 256, 256>>>(ei, E, n);
    scan_kernel<<<1, 1024>>>(n);
    scatter_edges_kernel<<<(etot + 255) / 256, 256>>>(ei, E, n);

    // 2. h1 = x @ W1  [n,256]x[256,256]
    {
        dim3 grid(D1 / 128, (n + 127) / 128);
        sgemm_kernel<128, 128, 16, 8, 8><<<grid, 256>>>(n, D1, DIN, x, W1, h1);
    }
    s1_kernel<<<(n * 32 + 255) / 256, 256>>>(as1, ad1, n);
    edge1_kernel<<<(etot + 255) / 256, 256>>>(etot);

    // 3. layer-1 softmax aggregate + swish mix -> x1
    gat1_kernel<<<(n + 3) / 4, 256>>>(b1, n);

    // 4. h2 = x1 @ W2  [n,256]x[256,64]
    {
        dim3 grid(DOUT / 64, (n + 127) / 128);
        sgemm_kernel<128, 64, 16, 8, 4><<<grid, 256>>>(n, DOUT, D1, x1, W2, h2);
    }
    s2_kernel<<<(n * 32 + 255) / 256, 256>>>(as2, ad2, n);
    edge2_kernel<<<(etot + 255) / 256, 256>>>(etot);

    // 5. layer-2 aggregate -> out
    gat2_kernel<<<(n + 15) / 16, 256>>>(b2, out, n);
}

// round 9
// speedup vs baseline: 1.1633x; 1.1633x over previous
#include <cuda_runtime.h>
#include <cuda_bf16.h>

// ---------------------------------------------------------------------------
// MixGAT: 2-layer GAT on a random graph with self-loops.
//   N=50000 nodes, E=800000 edges (+N self loops), IN=256, H=4, HID=64, OUT=64
// R9 changes vs best (R6, 475us):
//   - GEMM1 -> tensor cores: split-bf16 3-pass (xh*wh + xl*wh + xh*wl) via
//     mma.sync.m16n8k16 with fp32 accum (~1e-5 rel err, far under 1e-3)
//   - gat/edge path reverted to R6 (R8 precompute was neutral: loops are
//     gather-latency bound, redundant exp was free)
//   - GEMM2 remains SIMT
// ---------------------------------------------------------------------------

#define N_NODES 50000
#define N_EDGES 800000
#define ETOT    (N_EDGES + N_NODES)
#define DIN     256
#define NH      4
#define HID     64
#define D1      256   // NH*HID
#define DOUT    64
#define SLOPE   0.2f
#define BETA    0.5f

// ---- scratch (device globals: allocation is forbidden) ----
__device__ float g_h1[N_NODES * D1];     // 51.2 MB
__device__ float g_x1[N_NODES * D1];     // 51.2 MB
__device__ float g_h2[N_NODES * DOUT];   // 12.8 MB
__device__ float g_s1s[N_NODES * NH];
__device__ float g_s1d[N_NODES * NH];
__device__ float g_s2s[N_NODES];
__device__ float g_s2d[N_NODES];
__device__ int   g_deg[N_NODES];
__device__ int   g_rowptr[N_NODES + 1];
__device__ int   g_wptr[N_NODES];
__device__ int   g_csr[ETOT];            // src node per (dst-sorted) edge
// split-bf16 operands for tensor-core GEMM1
__device__ __nv_bfloat16 g_xh[N_NODES * DIN];   // 25.6 MB
__device__ __nv_bfloat16 g_xl[N_NODES * DIN];   // 25.6 MB
__device__ __nv_bfloat16 g_w1h[DIN * D1];
__device__ __nv_bfloat16 g_w1l[DIN * D1];

// ---------------------------------------------------------------------------
// CSR build
// ---------------------------------------------------------------------------
__global__ void zero_deg_kernel(int n) {
    int i = blockIdx.x * blockDim.x + threadIdx.x;
    if (i < n) g_deg[i] = 0;
}

__global__ void count_edges_kernel(const int* __restrict__ ei, int E, int n) {
    int j = blockIdx.x * blockDim.x + threadIdx.x;
    int etot = E + n;
    if (j >= etot) return;
    int dst = (j < E) ? ei[E + j] : (j - E);  // self loops appended
    atomicAdd(&g_deg[dst], 1);
}

// single-block exclusive scan over g_deg -> g_rowptr, g_wptr
__global__ void scan_kernel(int n) {
    __shared__ int sh[1024];
    __shared__ int carry;
    int tid = threadIdx.x;
    if (tid == 0) carry = 0;
    __syncthreads();
    for (int base = 0; base < n; base += 1024) {
        int i = base + tid;
        int v = (i < n) ? g_deg[i] : 0;
        sh[tid] = v;
        __syncthreads();
        int val = v;
        #pragma unroll
        for (int off = 1; off < 1024; off <<= 1) {
            int t = (tid >= off) ? sh[tid - off] : 0;
            __syncthreads();
            val += t;
            sh[tid] = val;
            __syncthreads();
        }
        int excl = val - v;
        int c = carry;
        if (i < n) { g_rowptr[i] = c + excl; g_wptr[i] = c + excl; }
        __syncthreads();
        if (tid == 0) carry = c + sh[1023];
        __syncthreads();
    }
    if (tid == 0) g_rowptr[n] = carry;
}

__global__ void scatter_edges_kernel(const int* __restrict__ ei, int E, int n) {
    int j = blockIdx.x * blockDim.x + threadIdx.x;
    int etot = E + n;
    if (j >= etot) return;
    int src, dst;
    if (j < E) { src = ei[j]; dst = ei[E + j]; }
    else       { src = dst = j - E; }
    int p = atomicAdd(&g_wptr[dst], 1);
    g_csr[p] = src;
}

// ---------------------------------------------------------------------------
// split fp32 -> (bf16 hi, bf16 lo): hi = bf16(v), lo = bf16(v - hi)
// ---------------------------------------------------------------------------
__global__ __launch_bounds__(256) void split_kernel(
    const float* __restrict__ in,
    __nv_bfloat16* __restrict__ hi, __nv_bfloat16* __restrict__ lo, int n4)
{
    int i = blockIdx.x * blockDim.x + threadIdx.x;
    if (i >= n4) return;
    float4 v = *(const float4*)(in + i * 4);
    __nv_bfloat16 h0 = __float2bfloat16(v.x);
    __nv_bfloat16 h1 = __float2bfloat16(v.y);
    __nv_bfloat16 h2 = __float2bfloat16(v.z);
    __nv_bfloat16 h3 = __float2bfloat16(v.w);
    __nv_bfloat16 l0 = __float2bfloat16(v.x - __bfloat162float(h0));
    __nv_bfloat16 l1 = __float2bfloat16(v.y - __bfloat162float(h1));
    __nv_bfloat16 l2 = __float2bfloat16(v.z - __bfloat162float(h2));
    __nv_bfloat16 l3 = __float2bfloat16(v.w - __bfloat162float(h3));
    unsigned short* hp = (unsigned short*)hi;
    unsigned short* lp = (unsigned short*)lo;
    ushort4 hv, lv;
    hv.x = *(unsigned short*)&h0; hv.y = *(unsigned short*)&h1;
    hv.z = *(unsigned short*)&h2; hv.w = *(unsigned short*)&h3;
    lv.x = *(unsigned short*)&l0; lv.y = *(unsigned short*)&l1;
    lv.z = *(unsigned short*)&l2; lv.w = *(unsigned short*)&l3;
    *(ushort4*)(hp + i * 4) = hv;
    *(ushort4*)(lp + i * 4) = lv;
}

// ---------------------------------------------------------------------------
// tensor-core GEMM, split-bf16 3-pass: C = Ah*Bh + Al*Bh + Ah*Bl (fp32 accum)
// BM=64, BN=128, BK=32; 256 threads = 8 warps in 2(m) x 4(n); warp tile 32x32.
// A row-major [M,K]; B row-major [K,N] (transposed into smem for col frags).
// smem rows padded to 17 words (34 bf16) -> odd word stride, conflict-free.
// ---------------------------------------------------------------------------
__device__ __forceinline__ void mma_bf16(float* c, const unsigned* a, const unsigned* b) {
    asm volatile(
        "mma.sync.aligned.m16n8k16.row.col.f32.bf16.bf16.f32 "
        "{%0,%1,%2,%3}, {%4,%5,%6,%7}, {%8,%9}, {%0,%1,%2,%3};\n"
        : "+f"(c[0]), "+f"(c[1]), "+f"(c[2]), "+f"(c[3])
        : "r"(a[0]), "r"(a[1]), "r"(a[2]), "r"(a[3]), "r"(b[0]), "r"(b[1]));
}

__global__ __launch_bounds__(256) void gemm_bf16x3_kernel(
    int M, int N, int K,
    const __nv_bfloat16* __restrict__ Ah, const __nv_bfloat16* __restrict__ Al,
    const __nv_bfloat16* __restrict__ Bh, const __nv_bfloat16* __restrict__ Bl,
    float* __restrict__ C)
{
    __shared__ unsigned AsH[64 * 17], AsL[64 * 17];
    __shared__ unsigned BsH[128 * 17], BsL[128 * 17];
    const int tid = threadIdx.x;
    const int lane = tid & 31, warp = tid >> 5;
    const int g = lane >> 2, tig = lane & 3;
    const int wm0 = (warp & 1) * 32;       // warp m offset within 64
    const int wn0 = (warp >> 1) * 32;      // warp n offset within 128
    const int rowBase = blockIdx.y * 64;
    const int colBase = blockIdx.x * 128;

    float acc[2][4][4];
    #pragma unroll
    for (int m = 0; m < 2; m++)
        #pragma unroll
        for (int i = 0; i < 4; i++)
            #pragma unroll
            for (int q = 0; q < 4; q++) acc[m][i][q] = 0.f;

    for (int kt = 0; kt < K; kt += 32) {
        // A tile 64x32 (both arrays): 512 uint2 per array, 2 per thread
        #pragma unroll
        for (int i = 0; i < 2; i++) {
            int idx = tid + i * 256;           // 0..511
            int r = idx >> 3, c8 = idx & 7;    // c8 = uint2 index along k (8 per row)
            int gr = rowBase + r;
            uint2 vh = make_uint2(0u, 0u), vl = make_uint2(0u, 0u);
            if (gr < M) {
                vh = *(const uint2*)(Ah + (long)gr * K + kt + c8 * 4);
                vl = *(const uint2*)(Al + (long)gr * K + kt + c8 * 4);
            }
            AsH[r * 17 + c8 * 2] = vh.x; AsH[r * 17 + c8 * 2 + 1] = vh.y;
            AsL[r * 17 + c8 * 2] = vl.x; AsL[r * 17 + c8 * 2 + 1] = vl.y;
        }
        // B tile 32(k) x 128(n), store transposed [n][k] as bf16 scalars
        #pragma unroll
        for (int i = 0; i < 4; i++) {
            int idx = tid + i * 256;           // 0..1023
            int r = idx >> 5, c4 = idx & 31;   // r = k row, c4 = uint2 idx along n
            uint2 vh = *(const uint2*)(Bh + (long)(kt + r) * N + colBase + c4 * 4);
            uint2 vl = *(const uint2*)(Bl + (long)(kt + r) * N + colBase + c4 * 4);
            unsigned short* ph = (unsigned short*)&vh;
            unsigned short* pl = (unsigned short*)&vl;
            unsigned short* bsh = (unsigned short*)BsH;
            unsigned short* bsl = (unsigned short*)BsL;
            #pragma unroll
            for (int j = 0; j < 4; j++) {
                int nn = c4 * 4 + j;
                bsh[nn * 34 + r] = ph[j];
                bsl[nn * 34 + r] = pl[j];
            }
        }
        __syncthreads();

        #pragma unroll
        for (int kk = 0; kk < 2; kk++) {       // two k16 steps per BK=32
            int wb = kk * 8;                   // word base within row
            unsigned ah[2][4], al[2][4];
            #pragma unroll
            for (int m = 0; m < 2; m++) {
                int r0 = wm0 + m * 16 + g, r1 = r0 + 8;
                ah[m][0] = AsH[r0 * 17 + wb + tig];
                ah[m][1] = AsH[r1 * 17 + wb + tig];
                ah[m][2] = AsH[r0 * 17 + wb + 4 + tig];
                ah[m][3] = AsH[r1 * 17 + wb + 4 + tig];
                al[m][0] = AsL[r0 * 17 + wb + tig];
                al[m][1] = AsL[r1 * 17 + wb + tig];
                al[m][2] = AsL[r0 * 17 + wb + 4 + tig];
                al[m][3] = AsL[r1 * 17 + wb + 4 + tig];
            }
            unsigned bh[4][2], bl[4][2];
            #pragma unroll
            for (int i = 0; i < 4; i++) {
                int n0 = wn0 + 8 * i + g;
                bh[i][0] = BsH[n0 * 17 + wb + tig];
                bh[i][1] = BsH[n0 * 17 + wb + 4 + tig];
                bl[i][0] = BsL[n0 * 17 + wb + tig];
                bl[i][1] = BsL[n0 * 17 + wb + 4 + tig];
            }
            #pragma unroll
            for (int m = 0; m < 2; m++)
                #pragma unroll
                for (int i = 0; i < 4; i++) {
                    mma_bf16(acc[m][i], ah[m], bh[i]);   // hi*hi
                    mma_bf16(acc[m][i], al[m], bh[i]);   // lo*hi
                    mma_bf16(acc[m][i], ah[m], bl[i]);   // hi*lo
                }
        }
        __syncthreads();
    }

    // epilogue: c0=(g,2t) c1=(g,2t+1) c2=(g+8,2t) c3=(g+8,2t+1)
    #pragma unroll
    for (int m = 0; m < 2; m++) {
        #pragma unroll
        for (int i = 0; i < 4; i++) {
            int r0 = rowBase + wm0 + m * 16 + g;
            int c0 = colBase + wn0 + 8 * i + tig * 2;
            if (r0 < M)
                *(float2*)(C + (long)r0 * N + c0) = make_float2(acc[m][i][0], acc[m][i][1]);
            if (r0 + 8 < M)
                *(float2*)(C + (long)(r0 + 8) * N + c0) = make_float2(acc[m][i][2], acc[m][i][3]);
        }
    }
}

// ---------------------------------------------------------------------------
// SGEMM (SIMT, fp32) for GEMM2: BK=16, register-prefetch double buffering.
// ---------------------------------------------------------------------------
template <int BM, int BN, int BK, int TM, int TN>
__global__ __launch_bounds__(256) void sgemm_kernel(
    int M, int N, int K,
    const float* __restrict__ A, const float* __restrict__ B,
    float* __restrict__ C)
{
    const int NA = (BM * BK) / (256 * 4);
    const int NB = (BK * BN) / (256 * 4);
    __shared__ float As[BK][BM];
    __shared__ float Bs[BK][BN];
    const int tid = threadIdx.x;
    const int tx = tid % (BN / TN);
    const int ty = tid / (BN / TN);
    const int rowBase = blockIdx.y * BM;
    const int colBase = blockIdx.x * BN;

    float acc[TM][TN];
    #pragma unroll
    for (int m = 0; m < TM; m++)
        #pragma unroll
        for (int n = 0; n < TN; n++) acc[m][n] = 0.f;

    float4 ra[(BM * BK) / (256 * 4)];
    float4 rb[(BK * BN) / (256 * 4)];

    #pragma unroll
    for (int i = 0; i < NA; i++) {
        int idx = (tid + i * 256) * 4;
        int r = idx / BK, c = idx % BK;
        int gr = rowBase + r;
        if (gr < M) ra[i] = *(const float4*)(A + (long)gr * K + c);
        else        ra[i] = make_float4(0.f, 0.f, 0.f, 0.f);
    }
    #pragma unroll
    for (int i = 0; i < NB; i++) {
        int idx = (tid + i * 256) * 4;
        int r = idx / BN, c = idx % BN;
        rb[i] = *(const float4*)(B + (long)r * N + colBase + c);
    }

    for (int k0 = 0; k0 < K; k0 += BK) {
        #pragma unroll
        for (int i = 0; i < NA; i++) {
            int idx = (tid + i * 256) * 4;
            int r = idx / BK, c = idx % BK;
            As[c + 0][r] = ra[i].x; As[c + 1][r] = ra[i].y;
            As[c + 2][r] = ra[i].z; As[c + 3][r] = ra[i].w;
        }
        #pragma unroll
        for (int i = 0; i < NB; i++) {
            int idx = (tid + i * 256) * 4;
            int r = idx / BN, c = idx % BN;
            *(float4*)&Bs[r][c] = rb[i];
        }
        __syncthreads();

        int k1 = k0 + BK;
        if (k1 < K) {
            #pragma unroll
            for (int i = 0; i < NA; i++) {
                int idx = (tid + i * 256) * 4;
                int r = idx / BK, c = idx % BK;
                int gr = rowBase + r;
                if (gr < M) ra[i] = *(const float4*)(A + (long)gr * K + k1 + c);
                else        ra[i] = make_float4(0.f, 0.f, 0.f, 0.f);
            }
            #pragma unroll
            for (int i = 0; i < NB; i++) {
                int idx = (tid + i * 256) * 4;
                int r = idx / BN, c = idx % BN;
                rb[i] = *(const float4*)(B + (long)(k1 + r) * N + colBase + c);
            }
        }

        #pragma unroll
        for (int k = 0; k < BK; k++) {
            float af[TM], bf[TN];
            #pragma unroll
            for (int m = 0; m < TM; m++) af[m] = As[k][ty * TM + m];
            #pragma unroll
            for (int n = 0; n < TN; n++) bf[n] = Bs[k][tx * TN + n];
            #pragma unroll
            for (int m = 0; m < TM; m++)
                #pragma unroll
                for (int n = 0; n < TN; n++) acc[m][n] += af[m] * bf[n];
        }
        __syncthreads();
    }

    #pragma unroll
    for (int m = 0; m < TM; m++) {
        int gr = rowBase + ty * TM + m;
        if (gr >= M) continue;
        #pragma unroll
        for (int n = 0; n < TN; n += 4) {
            *(float4*)(C + (long)gr * N + colBase + tx * TN + n) =
                make_float4(acc[m][n], acc[m][n + 1], acc[m][n + 2], acc[m][n + 3]);
        }
    }
}

// ---------------------------------------------------------------------------
// attention logits
// ---------------------------------------------------------------------------
__global__ __launch_bounds__(256) void s1_kernel(
    const float* __restrict__ a_src, const float* __restrict__ a_dst, int n)
{
    int warp = (blockIdx.x * blockDim.x + threadIdx.x) >> 5;
    int lane = threadIdx.x & 31;
    if (warp >= n) return;
    const float* row = g_h1 + (long)warp * D1;
    float accs[4] = {0.f, 0.f, 0.f, 0.f};
    float accd[4] = {0.f, 0.f, 0.f, 0.f};
    #pragma unroll
    for (int j = 0; j < 8; j++) {
        int k = lane + 32 * j;          // head = j>>1
        float v = row[k];
        accs[j >> 1] += v * a_src[k];
        accd[j >> 1] += v * a_dst[k];
    }
    #pragma unroll
    for (int h = 0; h < 4; h++) {
        float s = accs[h], d = accd[h];
        #pragma unroll
        for (int off = 16; off; off >>= 1) {
            s += __shfl_down_sync(0xffffffffu, s, off);
            d += __shfl_down_sync(0xffffffffu, d, off);
        }
        if (lane == 0) { g_s1s[warp * NH + h] = s; g_s1d[warp * NH + h] = d; }
    }
}

__global__ __launch_bounds__(256) void s2_kernel(
    const float* __restrict__ a_src, const float* __restrict__ a_dst, int n)
{
    int warp = (blockIdx.x * blockDim.x + threadIdx.x) >> 5;
    int lane = threadIdx.x & 31;
    if (warp >= n) return;
    const float* row = g_h2 + (long)warp * DOUT;
    float v0 = row[lane], v1 = row[lane + 32];
    float s = v0 * a_src[lane] + v1 * a_src[lane + 32];
    float d = v0 * a_dst[lane] + v1 * a_dst[lane + 32];
    #pragma unroll
    for (int off = 16; off; off >>= 1) {
        s += __shfl_down_sync(0xffffffffu, s, off);
        d += __shfl_down_sync(0xffffffffu, d, off);
    }
    if (lane == 0) { g_s2s[warp] = s; g_s2d[warp] = d; }
}

// ---------------------------------------------------------------------------
// GAT layer 1 aggregate (R6 form): single pass, exp in-loop (free under
// gather latency), no max subtraction (shift-invariant, O(1) logits).
// 64 threads per node (4 nodes/block), float4 features, head = local>>4.
// ---------------------------------------------------------------------------
__global__ __launch_bounds__(256) void gat1_kernel(const float* __restrict__ b1, int n)
{
    int node = blockIdx.x * 4 + (threadIdx.x >> 6);
    if (node >= n) return;
    int local = threadIdx.x & 63;
    int head = local >> 4;
    float sd = g_s1d[node * NH + head];
    int beg = g_rowptr[node], end = g_rowptr[node + 1];

    const float4* h1v = (const float4*)g_h1;
    float denom = 0.f;
    float4 acc = make_float4(0.f, 0.f, 0.f, 0.f);
    #pragma unroll 2
    for (int j = beg; j < end; j++) {
        int src = g_csr[j];
        float e = g_s1s[src * NH + head] + sd;
        e = (e > 0.f) ? e : SLOPE * e;
        float ee = __expf(e);
        denom += ee;
        float4 h = h1v[(long)src * (D1 / 4) + local];
        acc.x += ee * h.x; acc.y += ee * h.y;
        acc.z += ee * h.z; acc.w += ee * h.w;
    }
    float inv = 1.f / denom;
    float z0 = acc.x * inv + b1[local * 4 + 0];
    float z1 = acc.y * inv + b1[local * 4 + 1];
    float z2 = acc.z * inv + b1[local * 4 + 2];
    float z3 = acc.w * inv + b1[local * 4 + 3];
    float4 o;
    o.x = BETA * z0 + (1.f - BETA) * z0 / (1.f + __expf(-z0));
    o.y = BETA * z1 + (1.f - BETA) * z1 / (1.f + __expf(-z1));
    o.z = BETA * z2 + (1.f - BETA) * z2 / (1.f + __expf(-z2));
    o.w = BETA * z3 + (1.f - BETA) * z3 / (1.f + __expf(-z3));
    *(float4*)(g_x1 + (long)node * D1 + local * 4) = o;
}

// GAT layer 2: 16 threads per node (16 nodes per 256-block), float4 features.
__global__ __launch_bounds__(256) void gat2_kernel(
    const float* __restrict__ b2, float* __restrict__ out, int n)
{
    int node = blockIdx.x * 16 + (threadIdx.x >> 4);
    if (node >= n) return;
    int local = threadIdx.x & 15;
    float sd = g_s2d[node];
    int beg = g_rowptr[node], end = g_rowptr[node + 1];

    const float4* h2v = (const float4*)g_h2;
    float denom = 0.f;
    float4 acc = make_float4(0.f, 0.f, 0.f, 0.f);
    #pragma unroll 2
    for (int j = beg; j < end; j++) {
        int src = g_csr[j];
        float e = g_s2s[src] + sd;
        e = (e > 0.f) ? e : SLOPE * e;
        float ee = __expf(e);
        denom += ee;
        float4 h = h2v[(long)src * (DOUT / 4) + local];
        acc.x += ee * h.x; acc.y += ee * h.y;
        acc.z += ee * h.z; acc.w += ee * h.w;
    }
    float inv = 1.f / denom;
    float o0 = acc.x * inv + b2[local * 4 + 0];
    float o1 = acc.y * inv + b2[local * 4 + 1];
    float o2 = acc.z * inv + b2[local * 4 + 2];
    float o3 = acc.w * inv + b2[local * 4 + 3];
    float* op = out + (long)node * DOUT + local * 4;
    op[0] = o0; op[1] = o1; op[2] = o2; op[3] = o3;  // CC=1, heads=1
}

// ---------------------------------------------------------------------------
extern "C" void kernel_launch(void* const* d_in, const int* in_sizes, int n_in,
                              void* d_out, int out_size)
{
    const float* x   = (const float*)d_in[0];
    const int*   ei  = (const int*)d_in[1];
    const float* W1  = (const float*)d_in[2];
    const float* as1 = (const float*)d_in[3];
    const float* ad1 = (const float*)d_in[4];
    const float* b1  = (const float*)d_in[5];
    const float* W2  = (const float*)d_in[6];
    const float* as2 = (const float*)d_in[7];
    const float* ad2 = (const float*)d_in[8];
    const float* b2  = (const float*)d_in[9];
    float* out = (float*)d_out;

    const int n = in_sizes[0] / DIN;      // 50000
    const int E = in_sizes[1] / 2;        // 800000
    const int etot = E + n;

    float *h1, *x1, *h2;
    __nv_bfloat16 *xh, *xl, *w1h, *w1l;
    cudaGetSymbolAddress((void**)&h1, g_h1);
    cudaGetSymbolAddress((void**)&x1, g_x1);
    cudaGetSymbolAddress((void**)&h2, g_h2);
    cudaGetSymbolAddress((void**)&xh, g_xh);
    cudaGetSymbolAddress((void**)&xl, g_xl);
    cudaGetSymbolAddress((void**)&w1h, g_w1h);
    cudaGetSymbolAddress((void**)&w1l, g_w1l);

    // 1. CSR build by dst (shared by both layers)
    zero_deg_kernel<<<(n + 255) / 256, 256>>>(n);
    count_edges_kernel<<<(etot + 255) / 256, 256>>>(ei, E, n);
    scan_kernel<<<1, 1024>>>(n);
    scatter_edges_kernel<<<(etot + 255) / 256, 256>>>(ei, E, n);

    // 2. split x, W1 to bf16 hi/lo; h1 = x @ W1 via tensor cores (3-pass)
    {
        int n4x = n * DIN / 4;
        split_kernel<<<(n4x + 255) / 256, 256>>>(x, xh, xl, n4x);
        int n4w = DIN * D1 / 4;
        split_kernel<<<(n4w + 255) / 256, 256>>>(W1, w1h, w1l, n4w);
        dim3 grid(D1 / 128, (n + 63) / 64);
        gemm_bf16x3_kernel<<<grid, 256>>>(n, D1, DIN, xh, xl, w1h, w1l, h1);
    }
    s1_kernel<<<(n * 32 + 255) / 256, 256>>>(as1, ad1, n);

    // 3. layer-1 softmax aggregate + swish mix -> x1
    gat1_kernel<<<(n + 3) / 4, 256>>>(b1, n);

    // 4. h2 = x1 @ W2  [n,256]x[256,64]  (SIMT)
    {
        dim3 grid(DOUT / 64, (n + 127) / 128);
        sgemm_kernel<128, 64, 16, 8, 4><<<grid, 256>>>(n, DOUT, D1, x1, W2, h2);
    }
    s2_kernel<<<(n * 32 + 255) / 256, 256>>>(as2, ad2, n);

    // 5. layer-2 aggregate -> out
    gat2_kernel<<<(n + 15) / 16, 256>>>(b2, out, n);
}

// round 10
// speedup vs baseline: 1.3890x; 1.1940x over previous
#include <cuda_runtime.h>
#include <cuda_bf16.h>

// ---------------------------------------------------------------------------
// MixGAT: 2-layer GAT on a random graph with self-loops.
//   N=50000 nodes, E=800000 edges (+N self loops), IN=256, H=4, HID=64, OUT=64
// R10 changes vs R9 (413.7us):
//   - GEMM2 -> tensor cores (split-bf16 3-pass, BM=128/BN=64 instantiation);
//     the hi/lo split of x1 is FUSED into gat1's epilogue (x1 was only ever
//     consumed by GEMM2, so no fp32 x1 is materialized at all)
//   - single-block scan -> two-level scan (block scan + top scan + offset add)
// ---------------------------------------------------------------------------

#define N_NODES 50000
#define N_EDGES 800000
#define ETOT    (N_EDGES + N_NODES)
#define DIN     256
#define NH      4
#define HID     64
#define D1      256   // NH*HID
#define DOUT    64
#define SLOPE   0.2f
#define BETA    0.5f

// ---- scratch (device globals: allocation is forbidden) ----
__device__ float g_h1[N_NODES * D1];     // 51.2 MB
__device__ float g_h2[N_NODES * DOUT];   // 12.8 MB
__device__ float g_s1s[N_NODES * NH];
__device__ float g_s1d[N_NODES * NH];
__device__ float g_s2s[N_NODES];
__device__ float g_s2d[N_NODES];
__device__ int   g_deg[N_NODES];
__device__ int   g_tmp[N_NODES];         // block-local exclusive scan
__device__ int   g_bsum[64];
__device__ int   g_boff[64];
__device__ int   g_rowptr[N_NODES + 1];
__device__ int   g_wptr[N_NODES];
__device__ int   g_csr[ETOT];            // src node per (dst-sorted) edge
// split-bf16 operands for tensor-core GEMMs
__device__ __nv_bfloat16 g_xh[N_NODES * DIN];    // 25.6 MB
__device__ __nv_bfloat16 g_xl[N_NODES * DIN];    // 25.6 MB
__device__ __nv_bfloat16 g_x1h[N_NODES * D1];    // 25.6 MB (gat1 output hi)
__device__ __nv_bfloat16 g_x1l[N_NODES * D1];    // 25.6 MB (gat1 output lo)
__device__ __nv_bfloat16 g_w1h[DIN * D1];
__device__ __nv_bfloat16 g_w1l[DIN * D1];
__device__ __nv_bfloat16 g_w2h[D1 * DOUT];
__device__ __nv_bfloat16 g_w2l[D1 * DOUT];

// ---------------------------------------------------------------------------
// CSR build
// ---------------------------------------------------------------------------
__global__ void zero_deg_kernel(int n) {
    int i = blockIdx.x * blockDim.x + threadIdx.x;
    if (i < n) g_deg[i] = 0;
}

__global__ void count_edges_kernel(const int* __restrict__ ei, int E, int n) {
    int j = blockIdx.x * blockDim.x + threadIdx.x;
    int etot = E + n;
    if (j >= etot) return;
    int dst = (j < E) ? ei[E + j] : (j - E);  // self loops appended
    atomicAdd(&g_deg[dst], 1);
}

// two-level scan: per-block 1024-wide scan -> top scan (<=64 blocks) -> add
__global__ __launch_bounds__(1024) void scan_block_kernel(int n) {
    __shared__ int sh[1024];
    int tid = threadIdx.x;
    int i = blockIdx.x * 1024 + tid;
    int v = (i < n) ? g_deg[i] : 0;
    sh[tid] = v;
    __syncthreads();
    int val = v;
    #pragma unroll
    for (int off = 1; off < 1024; off <<= 1) {
        int t = (tid >= off) ? sh[tid - off] : 0;
        __syncthreads();
        val += t;
        sh[tid] = val;
        __syncthreads();
    }
    if (i < n) g_tmp[i] = val - v;           // exclusive within block
    if (tid == 1023) g_bsum[blockIdx.x] = val;
}

__global__ void scan_top_kernel(int nb, int n) {
    __shared__ int sh[64];
    int tid = threadIdx.x;                    // blockDim = 64
    int v = (tid < nb) ? g_bsum[tid] : 0;
    sh[tid] = v;
    __syncthreads();
    int val = v;
    #pragma unroll
    for (int off = 1; off < 64; off <<= 1) {
        int t = (tid >= off) ? sh[tid - off] : 0;
        __syncthreads();
        val += t;
        sh[tid] = val;
        __syncthreads();
    }
    g_boff[tid] = val - v;                    // exclusive block offsets
    if (tid == 63) g_rowptr[n] = val;         // grand total
}

__global__ __launch_bounds__(256) void scan_add_kernel(int n) {
    int i = blockIdx.x * blockDim.x + threadIdx.x;
    if (i >= n) return;
    int r = g_tmp[i] + g_boff[i >> 10];
    g_rowptr[i] = r;
    g_wptr[i] = r;
}

__global__ void scatter_edges_kernel(const int* __restrict__ ei, int E, int n) {
    int j = blockIdx.x * blockDim.x + threadIdx.x;
    int etot = E + n;
    if (j >= etot) return;
    int src, dst;
    if (j < E) { src = ei[j]; dst = ei[E + j]; }
    else       { src = dst = j - E; }
    int p = atomicAdd(&g_wptr[dst], 1);
    g_csr[p] = src;
}

// ---------------------------------------------------------------------------
// split fp32 -> (bf16 hi, bf16 lo): hi = bf16(v), lo = bf16(v - hi)
// ---------------------------------------------------------------------------
__global__ __launch_bounds__(256) void split_kernel(
    const float* __restrict__ in,
    __nv_bfloat16* __restrict__ hi, __nv_bfloat16* __restrict__ lo, int n4)
{
    int i = blockIdx.x * blockDim.x + threadIdx.x;
    if (i >= n4) return;
    float4 v = *(const float4*)(in + i * 4);
    __nv_bfloat16 h0 = __float2bfloat16(v.x);
    __nv_bfloat16 h1 = __float2bfloat16(v.y);
    __nv_bfloat16 h2 = __float2bfloat16(v.z);
    __nv_bfloat16 h3 = __float2bfloat16(v.w);
    __nv_bfloat16 l0 = __float2bfloat16(v.x - __bfloat162float(h0));
    __nv_bfloat16 l1 = __float2bfloat16(v.y - __bfloat162float(h1));
    __nv_bfloat16 l2 = __float2bfloat16(v.z - __bfloat162float(h2));
    __nv_bfloat16 l3 = __float2bfloat16(v.w - __bfloat162float(h3));
    unsigned short* hp = (unsigned short*)hi;
    unsigned short* lp = (unsigned short*)lo;
    ushort4 hv, lv;
    hv.x = *(unsigned short*)&h0; hv.y = *(unsigned short*)&h1;
    hv.z = *(unsigned short*)&h2; hv.w = *(unsigned short*)&h3;
    lv.x = *(unsigned short*)&l0; lv.y = *(unsigned short*)&l1;
    lv.z = *(unsigned short*)&l2; lv.w = *(unsigned short*)&l3;
    *(ushort4*)(hp + i * 4) = hv;
    *(ushort4*)(lp + i * 4) = lv;
}

// ---------------------------------------------------------------------------
// tensor-core GEMM, split-bf16 3-pass: C = Ah*Bh + Al*Bh + Ah*Bl (fp32 accum)
// Template on tile: 8 warps = (BM/32) x (BN/32), warp tile 32x32, BK=32.
// A row-major [M,K]; B row-major [K,N] transposed into smem.
// smem rows padded to 17 words -> conflict-free.
// ---------------------------------------------------------------------------
__device__ __forceinline__ void mma_bf16(float* c, const unsigned* a, const unsigned* b) {
    asm volatile(
        "mma.sync.aligned.m16n8k16.row.col.f32.bf16.bf16.f32 "
        "{%0,%1,%2,%3}, {%4,%5,%6,%7}, {%8,%9}, {%0,%1,%2,%3};\n"
        : "+f"(c[0]), "+f"(c[1]), "+f"(c[2]), "+f"(c[3])
        : "r"(a[0]), "r"(a[1]), "r"(a[2]), "r"(a[3]), "r"(b[0]), "r"(b[1]));
}

template <int BM, int BN>
__global__ __launch_bounds__(256) void gemm_bf16x3_kernel(
    int M, int N, int K,
    const __nv_bfloat16* __restrict__ Ah, const __nv_bfloat16* __restrict__ Al,
    const __nv_bfloat16* __restrict__ Bh, const __nv_bfloat16* __restrict__ Bl,
    float* __restrict__ C)
{
    __shared__ unsigned AsH[BM * 17], AsL[BM * 17];
    __shared__ unsigned BsH[BN * 17], BsL[BN * 17];
    const int tid = threadIdx.x;
    const int lane = tid & 31, warp = tid >> 5;
    const int g = lane >> 2, tig = lane & 3;
    const int WM = BM / 32;                    // warps in m
    const int wm0 = (warp % WM) * 32;
    const int wn0 = (warp / WM) * 32;
    const int rowBase = blockIdx.y * BM;
    const int colBase = blockIdx.x * BN;
    const int NA = BM / 32;                    // A uint2-loads per thread per array
    const int NB = BN / 32;                    // B uint2-loads per thread per array
    const int BN4 = BN / 4;                    // uint2 per B row

    float acc[2][4][4];
    #pragma unroll
    for (int m = 0; m < 2; m++)
        #pragma unroll
        for (int i = 0; i < 4; i++)
            #pragma unroll
            for (int q = 0; q < 4; q++) acc[m][i][q] = 0.f;

    for (int kt = 0; kt < K; kt += 32) {
        // A tile BM x 32: BM*8 uint2 per array
        #pragma unroll
        for (int i = 0; i < NA; i++) {
            int idx = tid + i * 256;
            int r = idx >> 3, c8 = idx & 7;
            int gr = rowBase + r;
            uint2 vh = make_uint2(0u, 0u), vl = make_uint2(0u, 0u);
            if (gr < M) {
                vh = *(const uint2*)(Ah + (long)gr * K + kt + c8 * 4);
                vl = *(const uint2*)(Al + (long)gr * K + kt + c8 * 4);
            }
            AsH[r * 17 + c8 * 2] = vh.x; AsH[r * 17 + c8 * 2 + 1] = vh.y;
            AsL[r * 17 + c8 * 2] = vl.x; AsL[r * 17 + c8 * 2 + 1] = vl.y;
        }
        // B tile 32(k) x BN(n): 32*BN/4 uint2, store transposed [n][k] bf16
        #pragma unroll
        for (int i = 0; i < NB; i++) {
            int idx = tid + i * 256;
            int r = idx / BN4, c4 = idx % BN4;
            uint2 vh = *(const uint2*)(Bh + (long)(kt + r) * N + colBase + c4 * 4);
            uint2 vl = *(const uint2*)(Bl + (long)(kt + r) * N + colBase + c4 * 4);
            unsigned short* ph = (unsigned short*)&vh;
            unsigned short* pl = (unsigned short*)&vl;
            unsigned short* bsh = (unsigned short*)BsH;
            unsigned short* bsl = (unsigned short*)BsL;
            #pragma unroll
            for (int j = 0; j < 4; j++) {
                int nn = c4 * 4 + j;
                bsh[nn * 34 + r] = ph[j];
                bsl[nn * 34 + r] = pl[j];
            }
        }
        __syncthreads();

        #pragma unroll
        for (int kk = 0; kk < 2; kk++) {       // two k16 steps per BK=32
            int wb = kk * 8;
            unsigned ah[2][4], al[2][4];
            #pragma unroll
            for (int m = 0; m < 2; m++) {
                int r0 = wm0 + m * 16 + g, r1 = r0 + 8;
                ah[m][0] = AsH[r0 * 17 + wb + tig];
                ah[m][1] = AsH[r1 * 17 + wb + tig];
                ah[m][2] = AsH[r0 * 17 + wb + 4 + tig];
                ah[m][3] = AsH[r1 * 17 + wb + 4 + tig];
                al[m][0] = AsL[r0 * 17 + wb + tig];
                al[m][1] = AsL[r1 * 17 + wb + tig];
                al[m][2] = AsL[r0 * 17 + wb + 4 + tig];
                al[m][3] = AsL[r1 * 17 + wb + 4 + tig];
            }
            unsigned bh[4][2], bl[4][2];
            #pragma unroll
            for (int i = 0; i < 4; i++) {
                int n0 = wn0 + 8 * i + g;
                bh[i][0] = BsH[n0 * 17 + wb + tig];
                bh[i][1] = BsH[n0 * 17 + wb + 4 + tig];
                bl[i][0] = BsL[n0 * 17 + wb + tig];
                bl[i][1] = BsL[n0 * 17 + wb + 4 + tig];
            }
            #pragma unroll
            for (int m = 0; m < 2; m++)
                #pragma unroll
                for (int i = 0; i < 4; i++) {
                    mma_bf16(acc[m][i], ah[m], bh[i]);   // hi*hi
                    mma_bf16(acc[m][i], al[m], bh[i]);   // lo*hi
                    mma_bf16(acc[m][i], ah[m], bl[i]);   // hi*lo
                }
        }
        __syncthreads();
    }

    #pragma unroll
    for (int m = 0; m < 2; m++) {
        #pragma unroll
        for (int i = 0; i < 4; i++) {
            int r0 = rowBase + wm0 + m * 16 + g;
            int c0 = colBase + wn0 + 8 * i + tig * 2;
            if (r0 < M)
                *(float2*)(C + (long)r0 * N + c0) = make_float2(acc[m][i][0], acc[m][i][1]);
            if (r0 + 8 < M)
                *(float2*)(C + (long)(r0 + 8) * N + c0) = make_float2(acc[m][i][2], acc[m][i][3]);
        }
    }
}

// ---------------------------------------------------------------------------
// attention logits
// ---------------------------------------------------------------------------
__global__ __launch_bounds__(256) void s1_kernel(
    const float* __restrict__ a_src, const float* __restrict__ a_dst, int n)
{
    int warp = (blockIdx.x * blockDim.x + threadIdx.x) >> 5;
    int lane = threadIdx.x & 31;
    if (warp >= n) return;
    const float* row = g_h1 + (long)warp * D1;
    float accs[4] = {0.f, 0.f, 0.f, 0.f};
    float accd[4] = {0.f, 0.f, 0.f, 0.f};
    #pragma unroll
    for (int j = 0; j < 8; j++) {
        int k = lane + 32 * j;          // head = j>>1
        float v = row[k];
        accs[j >> 1] += v * a_src[k];
        accd[j >> 1] += v * a_dst[k];
    }
    #pragma unroll
    for (int h = 0; h < 4; h++) {
        float s = accs[h], d = accd[h];
        #pragma unroll
        for (int off = 16; off; off >>= 1) {
            s += __shfl_down_sync(0xffffffffu, s, off);
            d += __shfl_down_sync(0xffffffffu, d, off);
        }
        if (lane == 0) { g_s1s[warp * NH + h] = s; g_s1d[warp * NH + h] = d; }
    }
}

__global__ __launch_bounds__(256) void s2_kernel(
    const float* __restrict__ a_src, const float* __restrict__ a_dst, int n)
{
    int warp = (blockIdx.x * blockDim.x + threadIdx.x) >> 5;
    int lane = threadIdx.x & 31;
    if (warp >= n) return;
    const float* row = g_h2 + (long)warp * DOUT;
    float v0 = row[lane], v1 = row[lane + 32];
    float s = v0 * a_src[lane] + v1 * a_src[lane + 32];
    float d = v0 * a_dst[lane] + v1 * a_dst[lane + 32];
    #pragma unroll
    for (int off = 16; off; off >>= 1) {
        s += __shfl_down_sync(0xffffffffu, s, off);
        d += __shfl_down_sync(0xffffffffu, d, off);
    }
    if (lane == 0) { g_s2s[warp] = s; g_s2d[warp] = d; }
}

// ---------------------------------------------------------------------------
// GAT layer 1 aggregate: single pass, exp in-loop (free under gather
// latency), no max subtraction (shift-invariant, O(1) logits).
// 64 threads/node (4 nodes/block), float4 features; epilogue writes the
// swish-mixed x1 directly as split bf16 hi/lo (consumed only by GEMM2).
// ---------------------------------------------------------------------------
__global__ __launch_bounds__(256) void gat1_kernel(const float* __restrict__ b1, int n)
{
    int node = blockIdx.x * 4 + (threadIdx.x >> 6);
    if (node >= n) return;
    int local = threadIdx.x & 63;
    int head = local >> 4;
    float sd = g_s1d[node * NH + head];
    int beg = g_rowptr[node], end = g_rowptr[node + 1];

    const float4* h1v = (const float4*)g_h1;
    float denom = 0.f;
    float4 acc = make_float4(0.f, 0.f, 0.f, 0.f);
    #pragma unroll 2
    for (int j = beg; j < end; j++) {
        int src = g_csr[j];
        float e = g_s1s[src * NH + head] + sd;
        e = (e > 0.f) ? e : SLOPE * e;
        float ee = __expf(e);
        denom += ee;
        float4 h = h1v[(long)src * (D1 / 4) + local];
        acc.x += ee * h.x; acc.y += ee * h.y;
        acc.z += ee * h.z; acc.w += ee * h.w;
    }
    float inv = 1.f / denom;
    float z0 = acc.x * inv + b1[local * 4 + 0];
    float z1 = acc.y * inv + b1[local * 4 + 1];
    float z2 = acc.z * inv + b1[local * 4 + 2];
    float z3 = acc.w * inv + b1[local * 4 + 3];
    // beta-mix swish, CC=1
    float o0 = BETA * z0 + (1.f - BETA) * z0 / (1.f + __expf(-z0));
    float o1 = BETA * z1 + (1.f - BETA) * z1 / (1.f + __expf(-z1));
    float o2 = BETA * z2 + (1.f - BETA) * z2 / (1.f + __expf(-z2));
    float o3 = BETA * z3 + (1.f - BETA) * z3 / (1.f + __expf(-z3));
    // fused hi/lo bf16 split (x1 feeds only the tensor-core GEMM2)
    __nv_bfloat16 h0 = __float2bfloat16(o0);
    __nv_bfloat16 h1b = __float2bfloat16(o1);
    __nv_bfloat16 h2b = __float2bfloat16(o2);
    __nv_bfloat16 h3 = __float2bfloat16(o3);
    __nv_bfloat16 l0 = __float2bfloat16(o0 - __bfloat162float(h0));
    __nv_bfloat16 l1 = __float2bfloat16(o1 - __bfloat162float(h1b));
    __nv_bfloat16 l2 = __float2bfloat16(o2 - __bfloat162float(h2b));
    __nv_bfloat16 l3 = __float2bfloat16(o3 - __bfloat162float(h3));
    ushort4 hv, lv;
    hv.x = *(unsigned short*)&h0; hv.y = *(unsigned short*)&h1b;
    hv.z = *(unsigned short*)&h2b; hv.w = *(unsigned short*)&h3;
    lv.x = *(unsigned short*)&l0; lv.y = *(unsigned short*)&l1;
    lv.z = *(unsigned short*)&l2; lv.w = *(unsigned short*)&l3;
    *(ushort4*)((unsigned short*)g_x1h + (long)node * D1 + local * 4) = hv;
    *(ushort4*)((unsigned short*)g_x1l + (long)node * D1 + local * 4) = lv;
}

// GAT layer 2: 16 threads per node (16 nodes per 256-block), float4 features.
__global__ __launch_bounds__(256) void gat2_kernel(
    const float* __restrict__ b2, float* __restrict__ out, int n)
{
    int node = blockIdx.x * 16 + (threadIdx.x >> 4);
    if (node >= n) return;
    int local = threadIdx.x & 15;
    float sd = g_s2d[node];
    int beg = g_rowptr[node], end = g_rowptr[node + 1];

    const float4* h2v = (const float4*)g_h2;
    float denom = 0.f;
    float4 acc = make_float4(0.f, 0.f, 0.f, 0.f);
    #pragma unroll 2
    for (int j = beg; j < end; j++) {
        int src = g_csr[j];
        float e = g_s2s[src] + sd;
        e = (e > 0.f) ? e : SLOPE * e;
        float ee = __expf(e);
        denom += ee;
        float4 h = h2v[(long)src * (DOUT / 4) + local];
        acc.x += ee * h.x; acc.y += ee * h.y;
        acc.z += ee * h.z; acc.w += ee * h.w;
    }
    float inv = 1.f / denom;
    float o0 = acc.x * inv + b2[local * 4 + 0];
    float o1 = acc.y * inv + b2[local * 4 + 1];
    float o2 = acc.z * inv + b2[local * 4 + 2];
    float o3 = acc.w * inv + b2[local * 4 + 3];
    float* op = out + (long)node * DOUT + local * 4;
    op[0] = o0; op[1] = o1; op[2] = o2; op[3] = o3;  // CC=1, heads=1
}

// ---------------------------------------------------------------------------
extern "C" void kernel_launch(void* const* d_in, const int* in_sizes, int n_in,
                              void* d_out, int out_size)
{
    const float* x   = (const float*)d_in[0];
    const int*   ei  = (const int*)d_in[1];
    const float* W1  = (const float*)d_in[2];
    const float* as1 = (const float*)d_in[3];
    const float* ad1 = (const float*)d_in[4];
    const float* b1  = (const float*)d_in[5];
    const float* W2  = (const float*)d_in[6];
    const float* as2 = (const float*)d_in[7];
    const float* ad2 = (const float*)d_in[8];
    const float* b2  = (const float*)d_in[9];
    float* out = (float*)d_out;

    const int n = in_sizes[0] / DIN;      // 50000
    const int E = in_sizes[1] / 2;        // 800000
    const int etot = E + n;
    const int nblk = (n + 1023) / 1024;   // 49 <= 64

    float *h1, *h2;
    __nv_bfloat16 *xh, *xl, *x1h, *x1l, *w1h, *w1l, *w2h, *w2l;
    cudaGetSymbolAddress((void**)&h1, g_h1);
    cudaGetSymbolAddress((void**)&h2, g_h2);
    cudaGetSymbolAddress((void**)&xh, g_xh);
    cudaGetSymbolAddress((void**)&xl, g_xl);
    cudaGetSymbolAddress((void**)&x1h, g_x1h);
    cudaGetSymbolAddress((void**)&x1l, g_x1l);
    cudaGetSymbolAddress((void**)&w1h, g_w1h);
    cudaGetSymbolAddress((void**)&w1l, g_w1l);
    cudaGetSymbolAddress((void**)&w2h, g_w2h);
    cudaGetSymbolAddress((void**)&w2l, g_w2l);

    // 1. CSR build by dst (shared by both layers); two-level scan
    zero_deg_kernel<<<(n + 255) / 256, 256>>>(n);
    count_edges_kernel<<<(etot + 255) / 256, 256>>>(ei, E, n);
    scan_block_kernel<<<nblk, 1024>>>(n);
    scan_top_kernel<<<1, 64>>>(nblk, n);
    scan_add_kernel<<<(n + 255) / 256, 256>>>(n);
    scatter_edges_kernel<<<(etot + 255) / 256, 256>>>(ei, E, n);

    // 2. split x, W1, W2; h1 = x @ W1 via tensor cores (3-pass)
    {
        int n4x = n * DIN / 4;
        split_kernel<<<(n4x + 255) / 256, 256>>>(x, xh, xl, n4x);
        int n4w = DIN * D1 / 4;
        split_kernel<<<(n4w + 255) / 256, 256>>>(W1, w1h, w1l, n4w);
        int n4w2 = D1 * DOUT / 4;
        split_kernel<<<(n4w2 + 255) / 256, 256>>>(W2, w2h, w2l, n4w2);
        dim3 grid(D1 / 128, (n + 63) / 64);
        gemm_bf16x3_kernel<64, 128><<<grid, 256>>>(n, D1, DIN, xh, xl, w1h, w1l, h1);
    }
    s1_kernel<<<(n * 32 + 255) / 256, 256>>>(as1, ad1, n);

    // 3. layer-1 softmax aggregate + swish mix -> x1 (split bf16, fused)
    gat1_kernel<<<(n + 3) / 4, 256>>>(b1, n);

    // 4. h2 = x1 @ W2  [n,256]x[256,64] via tensor cores (3-pass)
    {
        dim3 grid(DOUT / 64, (n + 127) / 128);
        gemm_bf16x3_kernel<128, 64><<<grid, 256>>>(n, DOUT, D1, x1h, x1l, w2h, w2l, h2);
    }
    s2_kernel<<<(n * 32 + 255) / 256, 256>>>(as2, ad2, n);

    // 5. layer-2 aggregate -> out
    gat2_kernel<<<(n + 15) / 16, 256>>>(b2, out, n);
}